// round 1
// baseline (speedup 1.0000x reference)
#include <cuda_runtime.h>
#include <cuda_bf16.h>

// Problem constants (match reference_code)
#define NV     100000      // vertices
#define EFULL  3200000     // directed edges
#define E2     1600000     // undirected edges (EFULL/2)
#define NB     8
#define NC     3
#define BC     24          // NB*NC, 96 bytes per vertex row
#define NTOT   (NB*NV*NC)  // 2,400,000

// Scratch (static device globals; no allocation anywhere)
__device__ int   g_deg[NV];
__device__ float g_dinv[NV];
__device__ float g_d  [NV * BC];   // d = x - y, layout (V, B*C)
__device__ float g_out[NV * BC];   // L d

// ---------------------------------------------------------------------------
// vectorized global reduction: red.global.add.v4.f32 (sm_90+)
__device__ __forceinline__ void red_add_v4(float* p, float a, float b, float c, float d) {
    asm volatile("red.global.add.v4.f32 [%0], {%1, %2, %3, %4};"
                 :: "l"(p), "f"(a), "f"(b), "f"(c), "f"(d) : "memory");
}

// ---------------------------------------------------------------------------
// K1: zero degree counters + zero the scalar output
__global__ void k_init(float* __restrict__ out) {
    int i = blockIdx.x * blockDim.x + threadIdx.x;
    if (i < NV) g_deg[i] = 0;
    if (i == 0) out[0] = 0.0f;
}

// K2: degree. row array = [src(E2) | dst(E2)] ; count both halves.
__global__ void k_deg(const int* __restrict__ ei) {
    int e = blockIdx.x * blockDim.x + threadIdx.x;
    if (e >= E2) return;
    int r = __ldg(ei + e);        // src[e]
    int c = __ldg(ei + E2 + e);   // dst[e]
    atomicAdd(&g_deg[r], 1);
    atomicAdd(&g_deg[c], 1);
}

// K3: deg_inv_sqrt
__global__ void k_dinv() {
    int i = blockIdx.x * blockDim.x + threadIdx.x;
    if (i >= NV) return;
    int d = g_deg[i];
    g_dinv[i] = (d > 0) ? rsqrtf((float)d) : 0.0f;
}

// K4: d = x - y, transposed to (V, B*C); out initialized to d (self-loop term).
// One thread per (v,b) pair -> 3 contiguous floats in, 3 contiguous floats out.
__global__ void k_diff(const float* __restrict__ x, const float* __restrict__ y) {
    int t = blockIdx.x * blockDim.x + threadIdx.x;
    if (t >= NV * NB) return;
    int v = t % NV;
    int b = t / NV;
    int bi = b * (NV * NC) + v * NC;   // source index (B,V,C) row-major
    int bo = v * BC + b * NC;          // dest index   (V,B*C)
    float a0 = __ldg(x + bi + 0) - __ldg(y + bi + 0);
    float a1 = __ldg(x + bi + 1) - __ldg(y + bi + 1);
    float a2 = __ldg(x + bi + 2) - __ldg(y + bi + 2);
    g_d[bo + 0] = a0;  g_out[bo + 0] = a0;
    g_d[bo + 1] = a1;  g_out[bo + 1] = a1;
    g_d[bo + 2] = a2;  g_out[bo + 2] = a2;
}

// K5: edge scatter. One thread per undirected edge, both directions.
// out[c] += w * d[r];  out[r] += w * d[c];  w = -dinv[r]*dinv[c]
__global__ void k_scatter(const int* __restrict__ ei) {
    int e = blockIdx.x * blockDim.x + threadIdx.x;
    if (e >= E2) return;
    int r = __ldg(ei + e);
    int c = __ldg(ei + E2 + e);
    float w = -__ldg(&g_dinv[r]) * __ldg(&g_dinv[c]);

    const float4* sr = (const float4*)(g_d + (size_t)r * BC);
    const float4* sc = (const float4*)(g_d + (size_t)c * BC);
    float* dr = g_out + (size_t)r * BC;
    float* dc = g_out + (size_t)c * BC;

#pragma unroll
    for (int i = 0; i < 6; i++) {
        float4 vr = __ldg(sr + i);
        float4 vc = __ldg(sc + i);
        red_add_v4(dc + 4 * i, w * vr.x, w * vr.y, w * vr.z, w * vr.w);
        red_add_v4(dr + 4 * i, w * vc.x, w * vc.y, w * vc.z, w * vc.w);
    }
}

// K6: mean of squares -> d_out[0] (pre-zeroed by k_init)
__global__ void k_reduce(float* __restrict__ out) {
    __shared__ float warp_part[8];
    float acc = 0.0f;
    for (int i = blockIdx.x * blockDim.x + threadIdx.x; i < NTOT;
         i += gridDim.x * blockDim.x) {
        float v = g_out[i];
        acc += v * v;
    }
    // warp reduce
    for (int o = 16; o > 0; o >>= 1)
        acc += __shfl_down_sync(0xFFFFFFFFu, acc, o);
    int lane = threadIdx.x & 31, wid = threadIdx.x >> 5;
    if (lane == 0) warp_part[wid] = acc;
    __syncthreads();
    if (wid == 0) {
        acc = (lane < (blockDim.x >> 5)) ? warp_part[lane] : 0.0f;
        for (int o = 4; o > 0; o >>= 1)
            acc += __shfl_down_sync(0xFFFFFFFFu, acc, o);
        if (lane == 0)
            atomicAdd(out, acc * (1.0f / (float)NTOT));
    }
}

// ---------------------------------------------------------------------------
extern "C" void kernel_launch(void* const* d_in, const int* in_sizes, int n_in,
                              void* d_out, int out_size) {
    const float* x  = (const float*)d_in[0];   // features      (B,V,C)
    const float* y  = (const float*)d_in[1];   // target_feats  (B,V,C)
    const int*   ei = (const int*)d_in[2];     // edge_index    (2,E)
    float* out = (float*)d_out;

    const int T = 256;
    k_init   <<<(NV + T - 1) / T, T>>>(out);
    k_deg    <<<(E2 + T - 1) / T, T>>>(ei);
    k_dinv   <<<(NV + T - 1) / T, T>>>();
    k_diff   <<<(NV * NB + T - 1) / T, T>>>(x, y);
    k_scatter<<<(E2 + T - 1) / T, T>>>(ei);
    k_reduce <<<1024, T>>>(out);
}

// round 2
// speedup vs baseline: 1.3567x; 1.3567x over previous
#include <cuda_runtime.h>
#include <cuda_bf16.h>

// Problem constants (match reference_code)
#define NV     100000      // vertices
#define EFULL  3200000     // directed edges (rows = ei[0:E], cols = ei[E:2E])
#define E2     1600000     // EFULL/2
#define NB     8
#define NC     3
#define BC     24          // NB*NC, 96 bytes per vertex row
#define NTOT   (NB*NV*NC)  // 2,400,000

// Scan config: 112*256*4 = 114688 >= NV
#define SCAN_B 112
#define SCAN_T 256
#define SCAN_K 4

#define GATHER_BLOCKS ((NV * 32 + 255) / 256)   // 12500, warp per vertex

// Scratch (static device globals; no allocation anywhere)
__device__ int   g_deg[NV];
__device__ int   g_rowptr[NV];
__device__ int   g_cur[NV];
__device__ int   g_bsum[SCAN_B];
__device__ int   g_adj[EFULL];
__device__ float g_dinv[NV];
__device__ float g_d[NV * BC];        // d = x - y, layout (V, B*C)
__device__ float g_partial[GATHER_BLOCKS];

// ---------------------------------------------------------------------------
// K1: zero degree counters
__global__ void k_init() {
    int i = blockIdx.x * blockDim.x + threadIdx.x;
    if (i < NV) g_deg[i] = 0;
}

// K2: degree histogram over rows (= concat(src,dst) = both halves of ei[0:E])
__global__ void k_deg(const int* __restrict__ ei) {
    int e = blockIdx.x * blockDim.x + threadIdx.x;
    if (e >= E2) return;
    atomicAdd(&g_deg[__ldg(ei + e)], 1);
    atomicAdd(&g_deg[__ldg(ei + E2 + e)], 1);
}

// K3a: per-block partial sums of degree
__global__ void k_scan_part() {
    int tid  = threadIdx.x;
    int base = blockIdx.x * (SCAN_T * SCAN_K) + tid * SCAN_K;
    int s = 0;
#pragma unroll
    for (int k = 0; k < SCAN_K; k++) {
        int i = base + k;
        if (i < NV) s += g_deg[i];
    }
    __shared__ int ws[SCAN_T / 32];
    for (int o = 16; o; o >>= 1) s += __shfl_down_sync(0xFFFFFFFFu, s, o);
    if ((tid & 31) == 0) ws[tid >> 5] = s;
    __syncthreads();
    if (tid < 32) {
        int v = (tid < SCAN_T / 32) ? ws[tid] : 0;
        for (int o = 4; o; o >>= 1) v += __shfl_down_sync(0xFFFFFFFFu, v, o);
        if (tid == 0) g_bsum[blockIdx.x] = v;
    }
}

// K3b: exclusive scan of the SCAN_B block sums (single block)
__global__ void k_scan_mid() {
    int tid = threadIdx.x;                       // 128 threads
    int v = (tid < SCAN_B) ? g_bsum[tid] : 0;
    int lane = tid & 31, w = tid >> 5;
    int x = v;
    for (int o = 1; o < 32; o <<= 1) {
        int t = __shfl_up_sync(0xFFFFFFFFu, x, o);
        if (lane >= o) x += t;
    }
    __shared__ int wt[4];
    if (lane == 31) wt[w] = x;
    __syncthreads();
    int add = 0;
    for (int k = 0; k < w; k++) add += wt[k];
    x += add;
    if (tid < SCAN_B) g_bsum[tid] = x - v;       // exclusive
}

// K3c: final scan: write rowptr (exclusive start) + cursor copy; also dinv
__global__ void k_scan_final() {
    int tid  = threadIdx.x;
    int base = blockIdx.x * (SCAN_T * SCAN_K) + tid * SCAN_K;
    int loc[SCAN_K];
    int s = 0;
#pragma unroll
    for (int k = 0; k < SCAN_K; k++) {
        int i = base + k;
        loc[k] = (i < NV) ? g_deg[i] : 0;
        s += loc[k];
    }
    int lane = tid & 31, w = tid >> 5;
    int x = s;
    for (int o = 1; o < 32; o <<= 1) {
        int t = __shfl_up_sync(0xFFFFFFFFu, x, o);
        if (lane >= o) x += t;
    }
    __shared__ int wt[SCAN_T / 32];
    __shared__ int wo[SCAN_T / 32];
    if (lane == 31) wt[w] = x;
    __syncthreads();
    if (tid == 0) {
        int a = 0;
        for (int k = 0; k < SCAN_T / 32; k++) { wo[k] = a; a += wt[k]; }
    }
    __syncthreads();
    int excl = x - s + wo[w] + g_bsum[blockIdx.x];
#pragma unroll
    for (int k = 0; k < SCAN_K; k++) {
        int i = base + k;
        if (i < NV) {
            g_rowptr[i] = excl;
            g_cur[i]    = excl;
            g_dinv[i]   = (loc[k] > 0) ? rsqrtf((float)loc[k]) : 0.0f;
            excl += loc[k];
        }
    }
}

// K4: CSR fill. pos = cursor++, adj[pos] = col.
__global__ void k_fill(const int* __restrict__ ei) {
    int j = blockIdx.x * blockDim.x + threadIdx.x;
    if (j >= EFULL) return;
    int row = __ldg(ei + j);
    int col = __ldg(ei + EFULL + j);
    int pos = atomicAdd(&g_cur[row], 1);
    g_adj[pos] = col;
}

// K5: d = x - y, transposed to (V, B*C) via shared-memory staging.
// Block handles 32 vertices x 8 batches; reads coalesced, writes coalesced.
__global__ void k_diff(const float* __restrict__ x, const float* __restrict__ y) {
    __shared__ float sm[32 * 25];                 // row pad 25 to dodge conflicts
    int tid = threadIdx.x;                        // 256
    int v0  = blockIdx.x * 32;
    int b   = tid >> 5, vl = tid & 31;
    int bi  = b * (NV * NC) + (v0 + vl) * NC;
    float a0 = __ldg(x + bi + 0) - __ldg(y + bi + 0);
    float a1 = __ldg(x + bi + 1) - __ldg(y + bi + 1);
    float a2 = __ldg(x + bi + 2) - __ldg(y + bi + 2);
    int so = vl * 25 + b * 3;
    sm[so + 0] = a0; sm[so + 1] = a1; sm[so + 2] = a2;
    __syncthreads();
    int gbase = v0 * BC;
#pragma unroll
    for (int k = 0; k < 3; k++) {
        int idx = tid * 3 + k;                    // 0..767 contiguous
        g_d[gbase + idx] = sm[(idx / 24) * 25 + (idx % 24)];
    }
}

// K6: fused gather + squared-error reduction. One warp per vertex:
// lanes 0..23 own the 24-float feature row; loop over CSR neighbors.
__global__ void k_gather() {
    int gw   = (blockIdx.x * blockDim.x + threadIdx.x) >> 5;
    int lane = threadIdx.x & 31;
    float sq = 0.0f;
    if (gw < NV) {
        int start = __ldg(&g_rowptr[gw]);
        int deg   = __ldg(&g_deg[gw]);
        float acc = 0.0f;
        int i = 0;
        for (; i + 4 <= deg; i += 4) {
            int u0 = __ldg(g_adj + start + i + 0);
            int u1 = __ldg(g_adj + start + i + 1);
            int u2 = __ldg(g_adj + start + i + 2);
            int u3 = __ldg(g_adj + start + i + 3);
            float w0 = __ldg(g_dinv + u0);
            float w1 = __ldg(g_dinv + u1);
            float w2 = __ldg(g_dinv + u2);
            float w3 = __ldg(g_dinv + u3);
            if (lane < BC) {
                float d0 = __ldg(g_d + u0 * BC + lane);
                float d1 = __ldg(g_d + u1 * BC + lane);
                float d2 = __ldg(g_d + u2 * BC + lane);
                float d3 = __ldg(g_d + u3 * BC + lane);
                acc += w0 * d0 + w1 * d1 + w2 * d2 + w3 * d3;
            }
        }
        for (; i < deg; i++) {
            int u = __ldg(g_adj + start + i);
            float wu = __ldg(g_dinv + u);
            if (lane < BC) acc += wu * __ldg(g_d + u * BC + lane);
        }
        if (lane < BC) {
            float val = __ldg(g_d + gw * BC + lane) - __ldg(g_dinv + gw) * acc;
            sq = val * val;
        }
    }
    // block reduce -> one partial per block (no hot global atomic)
    for (int o = 16; o; o >>= 1) sq += __shfl_down_sync(0xFFFFFFFFu, sq, o);
    __shared__ float ws[8];
    if (lane == 0) ws[threadIdx.x >> 5] = sq;
    __syncthreads();
    if (threadIdx.x < 32) {
        float v = (threadIdx.x < 8) ? ws[threadIdx.x] : 0.0f;
        for (int o = 4; o; o >>= 1) v += __shfl_down_sync(0xFFFFFFFFu, v, o);
        if (threadIdx.x == 0) g_partial[blockIdx.x] = v;
    }
}

// K7: sum partials -> mean
__global__ void k_final(float* __restrict__ out) {
    float s = 0.0f;
    for (int i = threadIdx.x; i < GATHER_BLOCKS; i += 256) s += g_partial[i];
    for (int o = 16; o; o >>= 1) s += __shfl_down_sync(0xFFFFFFFFu, s, o);
    __shared__ float ws[8];
    int lane = threadIdx.x & 31, w = threadIdx.x >> 5;
    if (lane == 0) ws[w] = s;
    __syncthreads();
    if (threadIdx.x < 32) {
        float v = (threadIdx.x < 8) ? ws[threadIdx.x] : 0.0f;
        for (int o = 4; o; o >>= 1) v += __shfl_down_sync(0xFFFFFFFFu, v, o);
        if (threadIdx.x == 0) out[0] = v * (1.0f / (float)NTOT);
    }
}

// ---------------------------------------------------------------------------
extern "C" void kernel_launch(void* const* d_in, const int* in_sizes, int n_in,
                              void* d_out, int out_size) {
    const float* x  = (const float*)d_in[0];   // features      (B,V,C)
    const float* y  = (const float*)d_in[1];   // target_feats  (B,V,C)
    const int*   ei = (const int*)d_in[2];     // edge_index    (2,E)
    float* out = (float*)d_out;

    const int T = 256;
    k_init      <<<(NV + T - 1) / T, T>>>();
    k_deg       <<<(E2 + T - 1) / T, T>>>(ei);
    k_scan_part <<<SCAN_B, SCAN_T>>>();
    k_scan_mid  <<<1, 128>>>();
    k_scan_final<<<SCAN_B, SCAN_T>>>();
    k_fill      <<<(EFULL + T - 1) / T, T>>>(ei);
    k_diff      <<<NV / 32, T>>>(x, y);
    k_gather    <<<GATHER_BLOCKS, T>>>();
    k_final     <<<1, T>>>(out);
}